// round 1
// baseline (speedup 1.0000x reference)
#include <cuda_runtime.h>
#include <math.h>

#define NB        50
#define NF_DIST   1225          // 50*49/2
#define NF_ANG    48
#define NF_DIH    47
#define NFEAT     (NF_DIST + NF_ANG + 2*NF_DIH)   // 1367

__global__ __launch_bounds__(256)
void protein_feat_kernel(const float* __restrict__ data,
                         float* __restrict__ out,
                         int n_frames)
{
    __shared__ float sx[NB], sy[NB], sz[NB];

    const int frame = blockIdx.x;
    if (frame >= n_frames) return;

    const float* p = data + (size_t)frame * NB * 3;
    const int tid = threadIdx.x;

    // Stage beads into SoA shared arrays (150 floats)
    for (int t = tid; t < NB * 3; t += blockDim.x) {
        float v = p[t];
        int bead = t / 3;
        int c    = t - bead * 3;
        if (c == 0)      sx[bead] = v;
        else if (c == 1) sy[bead] = v;
        else             sz[bead] = v;
    }
    __syncthreads();

    float* o = out + (size_t)frame * NFEAT;

    for (int f = tid; f < NFEAT; f += blockDim.x) {
        float res;

        if (f < NF_DIST) {
            // Distances, ordered by pair separation inc=1..49 then start i.
            // C(m) = m*(99-m)/2 = #pairs with inc <= m. Find largest m with C(m) <= f.
            int m = (int)((99.0f - sqrtf(9801.0f - 8.0f * (float)f)) * 0.5f);
            if (m < 0) m = 0;
            while (m * (99 - m) / 2 > f) --m;                 // fixup down
            while ((m + 1) * (98 - m) / 2 <= f) ++m;          // fixup up: C(m+1)=(m+1)(98-m)/2
            const int inc = m + 1;
            const int i   = f - m * (99 - m) / 2;
            const int j   = i + inc;

            float dx = sx[j] - sx[i];
            float dy = sy[j] - sy[i];
            float dz = sz[j] - sz[i];
            res = sqrtf(fmaf(dx, dx, fmaf(dy, dy, dz * dz)));
        }
        else if (f < NF_DIST + NF_ANG) {
            // Planar angle at middle bead of (a, a+1, a+2)
            const int a = f - NF_DIST;
            float b1x = sx[a]     - sx[a + 1];
            float b1y = sy[a]     - sy[a + 1];
            float b1z = sz[a]     - sz[a + 1];
            float b2x = sx[a + 2] - sx[a + 1];
            float b2y = sy[a + 2] - sy[a + 1];
            float b2z = sz[a + 2] - sz[a + 1];

            float dot = fmaf(b1x, b2x, fmaf(b1y, b2y, b1z * b2z));
            float n1  = fmaf(b1x, b1x, fmaf(b1y, b1y, b1z * b1z));
            float n2  = fmaf(b2x, b2x, fmaf(b2y, b2y, b2z * b2z));
            float ct  = dot * rsqrtf(n1 * n2);
            ct = fminf(1.0f, fmaxf(-1.0f, ct));
            res = acosf(ct);
        }
        else {
            // Dihedral of (d, d+1, d+2, d+3): cos then sin blocks
            int d = f - (NF_DIST + NF_ANG);
            bool want_sin = false;
            if (d >= NF_DIH) { d -= NF_DIH; want_sin = true; }

            float ax = sx[d + 1] - sx[d];
            float ay = sy[d + 1] - sy[d];
            float az = sz[d + 1] - sz[d];
            float bx = sx[d + 2] - sx[d + 1];
            float by = sy[d + 2] - sy[d + 1];
            float bz = sz[d + 2] - sz[d + 1];
            float cx = sx[d + 3] - sx[d + 2];
            float cy = sy[d + 3] - sy[d + 2];
            float cz = sz[d + 3] - sz[d + 2];

            // p1 = a x b, p2 = b x c
            float p1x = ay * bz - az * by;
            float p1y = az * bx - ax * bz;
            float p1z = ax * by - ay * bx;
            float p2x = by * cz - bz * cy;
            float p2y = bz * cx - bx * cz;
            float p2z = bx * cy - by * cx;

            float n1sq = fmaf(p1x, p1x, fmaf(p1y, p1y, p1z * p1z));
            float n2sq = fmaf(p2x, p2x, fmaf(p2y, p2y, p2z * p2z));
            float inv12 = rsqrtf(n1sq * n2sq);

            if (!want_sin) {
                float dp = fmaf(p1x, p2x, fmaf(p1y, p2y, p1z * p2z));
                res = dp * inv12;
            } else {
                // cross(p1, p2) . b / (|p1||p2||b|)
                float qx = p1y * p2z - p1z * p2y;
                float qy = p1z * p2x - p1x * p2z;
                float qz = p1x * p2y - p1y * p2x;
                float num = fmaf(qx, bx, fmaf(qy, by, qz * bz));
                float bnsq = fmaf(bx, bx, fmaf(by, by, bz * bz));
                res = num * inv12 * rsqrtf(bnsq);
            }
        }

        o[f] = res;
    }
}

extern "C" void kernel_launch(void* const* d_in, const int* in_sizes, int n_in,
                              void* d_out, int out_size)
{
    const float* data = (const float*)d_in[0];
    float* out = (float*)d_out;
    const int n_frames = in_sizes[0] / (NB * 3);

    protein_feat_kernel<<<n_frames, 256>>>(data, out, n_frames);
}

// round 2
// speedup vs baseline: 1.7655x; 1.7655x over previous
#include <cuda_runtime.h>
#include <stdint.h>
#include <math.h>

#define NB        50
#define NF_DIST   1225          // 50*49/2
#define NF_ANG    48
#define NF_DIH    47
#define NFEAT     (NF_DIST + NF_ANG + 2*NF_DIH)   // 1367

// ---------------------------------------------------------------------------
// Compile-time table of distance pairs, packed i | (j << 6), in cgnet order:
// by pair separation inc = 1..49, then start index i.
// ---------------------------------------------------------------------------
struct PairTable { uint16_t v[NF_DIST]; };

constexpr PairTable make_pair_table() {
    PairTable t{};
    int f = 0;
    for (int inc = 1; inc < NB; ++inc)
        for (int i = 0; i < NB - inc; ++i)
            t.v[f++] = (uint16_t)(i | ((i + inc) << 6));
    return t;
}

__device__ constexpr PairTable g_pairs = make_pair_table();

__global__ __launch_bounds__(256)
void protein_feat_kernel(const float* __restrict__ data,
                         float* __restrict__ out,
                         int n_frames)
{
    __shared__ float4 sb[NB];   // padded bead coords: 1 LDS.128 per bead fetch

    const int frame = blockIdx.x;
    if (frame >= n_frames) return;

    const float* p = data + (size_t)frame * NB * 3;
    const int tid = threadIdx.x;

    if (tid < NB) {
        float x = p[3 * tid + 0];
        float y = p[3 * tid + 1];
        float z = p[3 * tid + 2];
        sb[tid] = make_float4(x, y, z, 0.0f);
    }
    __syncthreads();

    float* o = out + (size_t)frame * NFEAT;

    for (int f = tid; f < NFEAT; f += 256) {
        float res;

        if (f < NF_DIST) {
            const unsigned t = g_pairs.v[f];
            const int i = t & 63;
            const int j = t >> 6;
            const float4 A = sb[i];
            const float4 B = sb[j];
            const float dx = B.x - A.x;
            const float dy = B.y - A.y;
            const float dz = B.z - A.z;
            const float n = fmaf(dx, dx, fmaf(dy, dy, dz * dz));
            res = n * rsqrtf(n);                    // sqrt via single MUFU.RSQ
        }
        else if (f < NF_DIST + NF_ANG) {
            const int a = f - NF_DIST;
            const float4 P0 = sb[a];
            const float4 P1 = sb[a + 1];
            const float4 P2 = sb[a + 2];
            const float b1x = P0.x - P1.x, b1y = P0.y - P1.y, b1z = P0.z - P1.z;
            const float b2x = P2.x - P1.x, b2y = P2.y - P1.y, b2z = P2.z - P1.z;

            const float dot = fmaf(b1x, b2x, fmaf(b1y, b2y, b1z * b2z));
            const float n1  = fmaf(b1x, b1x, fmaf(b1y, b1y, b1z * b1z));
            const float n2  = fmaf(b2x, b2x, fmaf(b2y, b2y, b2z * b2z));
            float ct = dot * rsqrtf(n1 * n2);
            ct = fminf(1.0f, fmaxf(-1.0f, ct));
            res = acosf(ct);
        }
        else {
            int d = f - (NF_DIST + NF_ANG);
            const bool want_sin = d >= NF_DIH;
            if (want_sin) d -= NF_DIH;

            const float4 P0 = sb[d];
            const float4 P1 = sb[d + 1];
            const float4 P2 = sb[d + 2];
            const float4 P3 = sb[d + 3];

            const float ax = P1.x - P0.x, ay = P1.y - P0.y, az = P1.z - P0.z;
            const float bx = P2.x - P1.x, by = P2.y - P1.y, bz = P2.z - P1.z;
            const float cx = P3.x - P2.x, cy = P3.y - P2.y, cz = P3.z - P2.z;

            // p1 = a x b, p2 = b x c
            const float p1x = ay * bz - az * by;
            const float p1y = az * bx - ax * bz;
            const float p1z = ax * by - ay * bx;
            const float p2x = by * cz - bz * cy;
            const float p2y = bz * cx - bx * cz;
            const float p2z = bx * cy - by * cx;

            const float n1sq = fmaf(p1x, p1x, fmaf(p1y, p1y, p1z * p1z));
            const float n2sq = fmaf(p2x, p2x, fmaf(p2y, p2y, p2z * p2z));
            const float inv12 = rsqrtf(n1sq * n2sq);

            if (!want_sin) {
                const float dp = fmaf(p1x, p2x, fmaf(p1y, p2y, p1z * p2z));
                res = dp * inv12;
            } else {
                const float qx = p1y * p2z - p1z * p2y;
                const float qy = p1z * p2x - p1x * p2z;
                const float qz = p1x * p2y - p1y * p2x;
                const float num  = fmaf(qx, bx, fmaf(qy, by, qz * bz));
                const float bnsq = fmaf(bx, bx, fmaf(by, by, bz * bz));
                res = num * inv12 * rsqrtf(bnsq);
            }
        }

        o[f] = res;
    }
}

extern "C" void kernel_launch(void* const* d_in, const int* in_sizes, int n_in,
                              void* d_out, int out_size)
{
    const float* data = (const float*)d_in[0];
    float* out = (float*)d_out;
    const int n_frames = in_sizes[0] / (NB * 3);

    protein_feat_kernel<<<n_frames, 256>>>(data, out, n_frames);
}